// round 13
// baseline (speedup 1.0000x reference)
#include <cuda_runtime.h>
#include <cuda_fp16.h>
#include <cstdint>
#include <math.h>

#define B_  8
#define S_  1024
#define D_  1024
#define H_  16
#define E_  64
#define HE_ 1024
#define BS_ (B_*S_)
#define NT_ (S_/64)

// ---------------- scratch (device globals; no runtime allocation) ----------
__device__ float g_Sc[(size_t)H_*S_*S_];   // per-batch score scratch (L2-resident)
__device__ float g_TS[B_*H_*NT_*E_];
__device__ float g_P [B_*H_*(NT_+1)*E_];

// fp16 operands
__device__ __half g_X1h[(size_t)BS_*D_];
__device__ __half g_X2h[(size_t)BS_*D_];
__device__ __half g_AOh[(size_t)BS_*D_];       // attention output, fp16 hi
__device__ __half g_Wq [(size_t)HE_*D_];       // [N,K] K-major
__device__ __half g_Wkv[(size_t)2*HE_*D_];     // [2048,K]: rows 0..1023 Wk, 1024..2047 Wv
__device__ __half g_Wo [(size_t)HE_*D_];

// per-head fp16 operands for attention mma
__device__ __half g_Qh[(size_t)B_*H_*S_*E_];   // [bh][s][e]
__device__ __half g_Kh[(size_t)B_*H_*S_*E_];   // [bh][s][e]
__device__ __half g_Vth[(size_t)B_*H_*E_*S_];  // [bh][e][s]
__device__ __half g_Ah[(size_t)B_*H_*S_*S_];   // [bh][q][k] (hi only)

// ---------------- PTX helpers (baseline sm_80+) -----------------------------
__device__ __forceinline__ uint32_t smem_u32(const void* p) {
    uint32_t a;
    asm("{ .reg .u64 t; cvta.to.shared.u64 t, %1; cvt.u32.u64 %0, t; }" : "=r"(a) : "l"(p));
    return a;
}
__device__ __forceinline__ void cp16(uint32_t s, const void* g) {
    asm volatile("cp.async.cg.shared.global [%0], [%1], 16;" :: "r"(s), "l"(g));
}
#define CP_COMMIT() asm volatile("cp.async.commit_group;" ::: "memory")
#define CP_WAIT1()  asm volatile("cp.async.wait_group 1;" ::: "memory")
#define CP_WAIT0()  asm volatile("cp.async.wait_group 0;" ::: "memory")

#define LDSM4(r, a) \
    asm volatile("ldmatrix.sync.aligned.m8n8.x4.shared.b16 {%0,%1,%2,%3}, [%4];" \
        : "=r"((r)[0]), "=r"((r)[1]), "=r"((r)[2]), "=r"((r)[3]) : "r"(a))

#define MMAF16(c, a, b0v, b1v) \
    asm volatile("mma.sync.aligned.m16n8k16.row.col.f32.f16.f16.f32 " \
        "{%0,%1,%2,%3}, {%4,%5,%6,%7}, {%8,%9}, {%0,%1,%2,%3};" \
        : "+f"((c)[0]), "+f"((c)[1]), "+f"((c)[2]), "+f"((c)[3]) \
        : "r"((a)[0]), "r"((a)[1]), "r"((a)[2]), "r"((a)[3]), "r"(b0v), "r"(b1v))

// ---------------- pack kernels ---------------------------------------------
__global__ __launch_bounds__(256) void cvt_h_kernel(
    const float* __restrict__ in, __half* __restrict__ out, int n4)
{
    int i = blockIdx.x * 256 + threadIdx.x;
    if (i >= n4) return;
    float4 v = ((const float4*)in)[i];
    *(__half2*)(out + i*4)     = __half2(__float2half_rn(v.x), __float2half_rn(v.y));
    *(__half2*)(out + i*4 + 2) = __half2(__float2half_rn(v.z), __float2half_rn(v.w));
}

// W fp32 [K=1024, N=1024] -> Wt fp16 [N, 1024] K-major
__global__ __launch_bounds__(256) void pack_w_kernel(
    const float* __restrict__ W, __half* __restrict__ out)
{
    __shared__ float t[32][33];
    const int n0 = blockIdx.x * 32, k0 = blockIdx.y * 32;
    const int tx = threadIdx.x, ty = threadIdx.y;
    #pragma unroll
    for (int i = 0; i < 4; i++)
        t[ty + i*8][tx] = W[(size_t)(k0 + ty + i*8) * 1024 + n0 + tx];
    __syncthreads();
    #pragma unroll
    for (int i = 0; i < 4; i++)
        out[(size_t)(n0 + ty + i*8) * 1024 + k0 + tx] = __float2half_rn(t[tx][ty + i*8]);
}

// ---------------- GEMM (mma.sync fp16, K=1024, 4 warps x 64x64 tiles) ------
// modes: 0 = fp32 C row-major; 2 = per-head fp16 hi; 3 = per-head fp16 TRANSPOSED;
//        4 = fused KV: blockIdx.x<8 -> K (mode2, Oh/bias); else V (mode3, Oh2/bias2)
__global__ __launch_bounds__(128) void gemm_mma_kernel(
    const __half* __restrict__ Ap, const __half* __restrict__ Bp,
    const float* __restrict__ bias, float* __restrict__ C,
    __half* __restrict__ Oh, int mode,
    const float* __restrict__ bias2, __half* __restrict__ Oh2)
{
    extern __shared__ char smch[];
    const uint32_t sb = smem_u32(smch);
    const int tid = threadIdx.x;
    const int lane = tid & 31, wid = tid >> 5;
    const int wm = wid >> 1, wn = wid & 1;
    const size_t m0 = (size_t)blockIdx.y * 128;
    const size_t n0 = (size_t)blockIdx.x * 128;

    // loader: thread = one row (0..127), 4 x 16B chunks each for A and B
    const __half* gA0 = Ap + (m0 + tid) * D_;
    const __half* gB0 = Bp + (n0 + tid) * D_;
    const uint32_t smA = sb + tid * 80;
    const uint32_t smB = smA + 10240;

    float acc[4][8][4];
    #pragma unroll
    for (int a = 0; a < 4; a++)
        #pragma unroll
        for (int b = 0; b < 8; b++)
            #pragma unroll
            for (int c = 0; c < 4; c++) acc[a][b][c] = 0.f;

    #define LOADST(kt, st) do {                                        \
        const uint32_t so_ = (uint32_t)(st) * 20480u;                  \
        const __half* ga_ = gA0 + (size_t)(kt) * 32;                   \
        const __half* gb_ = gB0 + (size_t)(kt) * 32;                   \
        cp16(smA + so_,      ga_);                                     \
        cp16(smA + so_ + 16, ga_ + 8);                                 \
        cp16(smA + so_ + 32, ga_ + 16);                                \
        cp16(smA + so_ + 48, ga_ + 24);                                \
        cp16(smB + so_,      gb_);                                     \
        cp16(smB + so_ + 16, gb_ + 8);                                 \
        cp16(smB + so_ + 32, gb_ + 16);                                \
        cp16(smB + so_ + 48, gb_ + 24);                                \
        CP_COMMIT();                                                   \
    } while (0)

    LOADST(0, 0);
    LOADST(1, 1);

    const uint32_t aAddr = sb + (uint32_t)(wm*64 + (lane & 15)) * 80 + ((lane >> 4) << 4);
    const uint32_t bAddr = sb + 10240 +
        (uint32_t)(wn*64 + ((lane >> 3) & 1) * 8 + (lane & 7)) * 80 + ((lane >> 4) << 4);

    const int NKT = D_ / 32;   // 32
    #pragma unroll 1
    for (int kt = 0; kt < NKT; kt++) {
        const int st = kt % 3;
        CP_WAIT1();
        __syncthreads();
        if (kt + 2 < NKT) LOADST(kt + 2, (kt + 2) % 3);
        const uint32_t so = (uint32_t)st * 20480u;
        #pragma unroll
        for (int ks = 0; ks < 2; ks++) {
            uint32_t afr[4][4], bfr[4][4];
            #pragma unroll
            for (int mt = 0; mt < 4; mt++)
                LDSM4(afr[mt], aAddr + so + (uint32_t)mt*16*80 + ks*32);
            #pragma unroll
            for (int nt2 = 0; nt2 < 4; nt2++)
                LDSM4(bfr[nt2], bAddr + so + (uint32_t)nt2*16*80 + ks*32);
            #pragma unroll
            for (int mt = 0; mt < 4; mt++)
                #pragma unroll
                for (int nt = 0; nt < 8; nt++)
                    MMAF16(acc[mt][nt], afr[mt],
                           bfr[nt >> 1][nt & 1], bfr[nt >> 1][2 + (nt & 1)]);
        }
    }
    CP_WAIT0();

    const int crow = lane >> 2, ccol = (lane & 3) * 2;
    int emode = mode;
    const float* bb = bias;
    __half* oo = Oh;
    int nsub = 0;
    if (mode == 4) {
        if (blockIdx.x < 8) { emode = 2; }
        else { emode = 3; bb = bias2; oo = Oh2; nsub = 1024; }
    }

    if (emode == 0) {
        #pragma unroll
        for (int nt = 0; nt < 8; nt++) {
            const int n = (int)n0 + wn*64 + nt*8 + ccol;
            const float b0v = bb[n], b1v = bb[n + 1];
            #pragma unroll
            for (int mt = 0; mt < 4; mt++) {
                const size_t m = m0 + wm*64 + mt*16 + crow;
                float2 v0, v1;
                v0.x = acc[mt][nt][0] + b0v; v0.y = acc[mt][nt][1] + b1v;
                v1.x = acc[mt][nt][2] + b0v; v1.y = acc[mt][nt][3] + b1v;
                *(float2*)(C + m * 1024 + n)       = v0;
                *(float2*)(C + (m + 8) * 1024 + n) = v1;
            }
        }
    } else if (emode == 2) {
        #pragma unroll
        for (int nt = 0; nt < 8; nt++) {
            const int n = (int)n0 + wn*64 + nt*8 + ccol;
            const float b0v = bb[n], b1v = bb[n + 1];
            const int h = n >> 6, e = n & 63;
            #pragma unroll
            for (int mt = 0; mt < 4; mt++) {
                #pragma unroll
                for (int half = 0; half < 2; half++) {
                    const size_t m = m0 + wm*64 + mt*16 + crow + half*8;
                    const int b2 = (int)(m >> 10), s = (int)(m & 1023);
                    const size_t o = (((size_t)(b2*16 + h) * 1024 + s) * 64 + e);
                    *(__half2*)(oo + o) = __half2(
                        __float2half_rn(acc[mt][nt][half*2]     + b0v),
                        __float2half_rn(acc[mt][nt][half*2 + 1] + b1v));
                }
            }
        }
    } else {   // emode 3: transposed per-head [bh][e][s]
        #pragma unroll
        for (int nt = 0; nt < 8; nt++) {
            const int ng = (int)n0 + wn*64 + nt*8 + ccol;
            const int n = ng - nsub;
            const float b0v = bb[n], b1v = bb[n + 1];
            const int h = n >> 6, e = n & 63;
            #pragma unroll
            for (int mt = 0; mt < 4; mt++) {
                #pragma unroll
                for (int half = 0; half < 2; half++) {
                    const size_t m = m0 + wm*64 + mt*16 + crow + half*8;
                    const int b2 = (int)(m >> 10), s = (int)(m & 1023);
                    const size_t o0 = (((size_t)(b2*16 + h) * 64 + e)     << 10) + s;
                    const size_t o1 = (((size_t)(b2*16 + h) * 64 + e + 1) << 10) + s;
                    oo[o0] = __float2half_rn(acc[mt][nt][half*2]     + b0v);
                    oo[o1] = __float2half_rn(acc[mt][nt][half*2 + 1] + b1v);
                }
            }
        }
    }
    #undef LOADST
}

// ---------------- scores via mma (hi-only), quirks fused, per-batch --------
__global__ __launch_bounds__(128) void scores_mma_kernel(int b)
{
    const int kt = blockIdx.x, qt = blockIdx.y;
    if (kt > qt) return;
    const int h = blockIdx.z;
    const int bh = b * 16 + h;

    __shared__ __align__(16) char sm[2 * 64 * 144];
    const uint32_t sQH = smem_u32(sm);
    const uint32_t sKH = sQH + 9216;

    const int tid = threadIdx.x;
    const int lane = tid & 31, wid = tid >> 5;
    const int wm = wid >> 1, wn = wid & 1;

    const __half* gQH = g_Qh + ((size_t)bh * 1024 + qt*64) * 64;
    const __half* gKH = g_Kh + ((size_t)bh * 1024 + kt*64) * 64;
    #pragma unroll
    for (int i = tid; i < 512; i += 128) {
        const int r = i >> 3, c = i & 7;
        const size_t go = (size_t)r * 64 + c * 8;
        const uint32_t so = r * 144 + c * 16;
        *(uint4*)(sm + so)        = *(const uint4*)(gQH + go);
        *(uint4*)(sm + 9216 + so) = *(const uint4*)(gKH + go);
    }
    __syncthreads();

    float acc[2][4][4];
    #pragma unroll
    for (int a = 0; a < 2; a++)
        #pragma unroll
        for (int b2 = 0; b2 < 4; b2++)
            #pragma unroll
            for (int c = 0; c < 4; c++) acc[a][b2][c] = 0.f;

    const uint32_t aOff = (uint32_t)(wm*32 + (lane & 15)) * 144 + ((lane >> 4) << 4);
    const uint32_t bOff = (uint32_t)(wn*32 + ((lane >> 3) & 1)*8 + (lane & 7)) * 144 + ((lane >> 4) << 4);

    #pragma unroll
    for (int es = 0; es < 4; es++) {
        const uint32_t cb = es * 32;
        uint32_t ah[2][4], bh2[2][4];
        #pragma unroll
        for (int mt = 0; mt < 2; mt++)
            LDSM4(ah[mt], sQH + aOff + (uint32_t)mt*16*144 + cb);
        #pragma unroll
        for (int nt2 = 0; nt2 < 2; nt2++)
            LDSM4(bh2[nt2], sKH + bOff + (uint32_t)nt2*16*144 + cb);
        #pragma unroll
        for (int mt = 0; mt < 2; mt++)
            #pragma unroll
            for (int nt = 0; nt < 4; nt++)
                MMAF16(acc[mt][nt], ah[mt], bh2[nt>>1][nt&1], bh2[nt>>1][2+(nt&1)]);
    }

    const float scale = 0.35355339059327373f;  // 1/sqrt(8) batch-size quirk
    float* out = g_Sc + (size_t)h * S_ * S_;
    #pragma unroll
    for (int mt = 0; mt < 2; mt++) {
        #pragma unroll
        for (int half = 0; half < 2; half++) {
            const int q = qt*64 + wm*32 + mt*16 + (lane >> 2) + half*8;
            #pragma unroll
            for (int nt = 0; nt < 4; nt++) {
                const int k0 = kt*64 + wn*32 + nt*8 + (lane & 3)*2;
                float v0 = acc[mt][nt][half*2]     * scale;
                float v1 = acc[mt][nt][half*2 + 1] * scale;
                if (k0     > q || v0 == 0.0f) v0 = -1e9f;
                if (k0 + 1 > q || v1 == 0.0f) v1 = -1e9f;
                *(float2*)(out + (size_t)q * S_ + k0) = make_float2(v0, v1);
            }
        }
    }
}

// ---------------- softmax over heads -> fp16 attn (hi only), per-batch -----
__global__ void softmax_h_kernel(int b)
{
    const int k = blockIdx.x * 256 + threadIdx.x;
    const int q = blockIdx.y;
    const int kmax = ((q >> 6) + 1) << 6;
    if (k >= kmax) return;

    const size_t so = (size_t)q * S_ + k;
    const size_t hs = (size_t)S_ * S_;
    float s[H_];
    float m = -3.4e38f;
    #pragma unroll
    for (int h = 0; h < H_; h++) { s[h] = g_Sc[so + h * hs]; m = fmaxf(m, s[h]); }
    float Z = 0.f;
    #pragma unroll
    for (int h = 0; h < H_; h++) { s[h] = expf(s[h] - m); Z += s[h]; }
    const float inv = 1.0f / Z;
    const size_t ab = (size_t)b * H_ * S_ * S_ + so;
    #pragma unroll
    for (int h = 0; h < H_; h++)
        g_Ah[ab + h * hs] = __float2half_rn(s[h] * inv);
}

// ---------------- V tile sums (from transposed fp16 V) + prefix scan -------
__global__ void tilesum_kernel()
{
    const int blk = blockIdx.x;
    const int e = threadIdx.x;
    const int tt = blk & (NT_ - 1);
    const int bh = blk / NT_;
    const __half2* Vb = (const __half2*)(g_Vth + (((size_t)bh * 64 + e) << 10) + tt*64);
    float sum = 0.f;
    #pragma unroll
    for (int k = 0; k < 32; k++) {
        const __half2 v = Vb[k];
        sum += __half2float(v.x) + __half2float(v.y);
    }
    g_TS[((size_t)bh * NT_ + tt) * E_ + e] = sum;
}

__global__ void scan_kernel()
{
    const int id = blockIdx.x * 256 + threadIdx.x;
    const int e = id & 63, bh = id >> 6;
    float* P = g_P + (size_t)bh * (NT_ + 1) * E_;
    float p = 0.f;
    P[e] = 0.f;
    #pragma unroll
    for (int tt = 0; tt < NT_; tt++) {
        p += g_TS[((size_t)bh * NT_ + tt) * E_ + e];
        P[(tt + 1) * E_ + e] = p;
    }
}

// ---------------- attn @ V via mma + masked suffix (single launch) ---------
__global__ __launch_bounds__(128) void attnv_mma_kernel()
{
    const int qt = blockIdx.x, bh = blockIdx.y;
    const int b = bh >> 4, h = bh & 15;

    __shared__ __align__(16) char sm[2 * 64 * 144];
    const uint32_t sAH = smem_u32(sm);
    const uint32_t sVH = sAH + 9216;

    const int tid = threadIdx.x;
    const int lane = tid & 31, wid = tid >> 5;
    const int wm = wid >> 1, wn = wid & 1;

    float acc[2][4][4];
    #pragma unroll
    for (int a = 0; a < 2; a++)
        #pragma unroll
        for (int b2 = 0; b2 < 4; b2++)
            #pragma unroll
            for (int c = 0; c < 4; c++) acc[a][b2][c] = 0.f;

    const uint32_t aOff = (uint32_t)(wm*32 + (lane & 15)) * 144 + ((lane >> 4) << 4);
    const uint32_t bOff = (uint32_t)(wn*32 + ((lane >> 3) & 1)*8 + (lane & 7)) * 144 + ((lane >> 4) << 4);

    const __half* gAH0 = g_Ah + ((size_t)bh * 1024 + qt*64) * 1024;
    const __half* gVH0 = g_Vth + (size_t)bh * 64 * 1024;

    for (int kt = 0; kt <= qt; kt++) {
        __syncthreads();
        #pragma unroll
        for (int i = tid; i < 512; i += 128) {
            const int r = i >> 3, c = i & 7;
            const size_t go = (size_t)r * 1024 + kt*64 + c * 8;
            const uint32_t so = r * 144 + c * 16;
            *(uint4*)(sm + so)        = *(const uint4*)(gAH0 + go);
            *(uint4*)(sm + 9216 + so) = *(const uint4*)(gVH0 + go);
        }
        __syncthreads();

        #pragma unroll
        for (int ks = 0; ks < 4; ks++) {
            const uint32_t cb = ks * 32;
            uint32_t ah[2][4], vh[2][4];
            #pragma unroll
            for (int mt = 0; mt < 2; mt++)
                LDSM4(ah[mt], sAH + aOff + (uint32_t)mt*16*144 + cb);
            #pragma unroll
            for (int nt2 = 0; nt2 < 2; nt2++)
                LDSM4(vh[nt2], sVH + bOff + (uint32_t)nt2*16*144 + cb);
            #pragma unroll
            for (int mt = 0; mt < 2; mt++)
                #pragma unroll
                for (int nt = 0; nt < 4; nt++)
                    MMAF16(acc[mt][nt], ah[mt], vh[nt>>1][nt&1], vh[nt>>1][2+(nt&1)]);
        }
    }

    const float* P = g_P + (size_t)bh * (NT_ + 1) * E_;
    #pragma unroll
    for (int nt = 0; nt < 4; nt++) {
        const int e0 = wn*32 + nt*8 + (lane & 3)*2;
        const float s0 = (P[NT_*E_ + e0]     - P[(qt+1)*E_ + e0])     * 0.0625f;
        const float s1 = (P[NT_*E_ + e0 + 1] - P[(qt+1)*E_ + e0 + 1]) * 0.0625f;
        #pragma unroll
        for (int mt = 0; mt < 2; mt++) {
            #pragma unroll
            for (int half = 0; half < 2; half++) {
                const int q = wm*32 + mt*16 + (lane >> 2) + half*8;
                __half* base = g_AOh + ((size_t)(b*1024 + qt*64 + q)) * D_ + h*64 + e0;
                *(__half2*)(base) = __half2(
                    __float2half_rn(acc[mt][nt][half*2]     + s0),
                    __float2half_rn(acc[mt][nt][half*2 + 1] + s1));
            }
        }
    }
}

// ---------------- launch ---------------------------------------------------
extern "C" void kernel_launch(void* const* d_in, const int* in_sizes, int n_in,
                              void* d_out, int out_size)
{
    const float* X1 = (const float*)d_in[0];
    const float* X2 = (const float*)d_in[1];
    const float* Wq = (const float*)d_in[2];
    const float* bq = (const float*)d_in[3];
    const float* Wk = (const float*)d_in[4];
    const float* bk = (const float*)d_in[5];
    const float* Wv = (const float*)d_in[6];
    const float* bv = (const float*)d_in[7];
    const float* Wo = (const float*)d_in[8];
    const float* bo = (const float*)d_in[9];
    float* out = (float*)d_out;

    void *pX1h, *pX2h, *pAOh, *pWq, *pWkv, *pWo;
    void *pQh, *pKh, *pVth;
    cudaGetSymbolAddress(&pX1h, g_X1h); cudaGetSymbolAddress(&pX2h, g_X2h);
    cudaGetSymbolAddress(&pAOh, g_AOh);
    cudaGetSymbolAddress(&pWq, g_Wq); cudaGetSymbolAddress(&pWkv, g_Wkv);
    cudaGetSymbolAddress(&pWo, g_Wo);
    cudaGetSymbolAddress(&pQh, g_Qh); cudaGetSymbolAddress(&pKh, g_Kh);
    cudaGetSymbolAddress(&pVth, g_Vth);

    const uint32_t SMEM_G = 61440;
    cudaFuncSetAttribute(gemm_mma_kernel,
                         cudaFuncAttributeMaxDynamicSharedMemorySize, SMEM_G);

    const int n4x = BS_ * D_ / 4;
    cvt_h_kernel<<<n4x / 256, 256>>>(X1, (__half*)pX1h, n4x);
    cvt_h_kernel<<<n4x / 256, 256>>>(X2, (__half*)pX2h, n4x);

    const dim3 gT(32, 32), bT(32, 8);
    pack_w_kernel<<<gT, bT>>>(Wq, (__half*)pWq);
    pack_w_kernel<<<gT, bT>>>(Wk, (__half*)pWkv);
    pack_w_kernel<<<gT, bT>>>(Wv, (__half*)pWkv + (size_t)1024*1024);
    pack_w_kernel<<<gT, bT>>>(Wo, (__half*)pWo);

    // Q projection -> per-head fp16 hi
    gemm_mma_kernel<<<dim3(8, 64), 128, SMEM_G>>>(
        (__half*)pX1h, (__half*)pWq, bq, nullptr, (__half*)pQh, 2, nullptr, nullptr);
    // fused K+V projection: nb<8 -> Kh (mode2), nb>=8 -> Vth transposed (mode3)
    gemm_mma_kernel<<<dim3(16, 64), 128, SMEM_G>>>(
        (__half*)pX2h, (__half*)pWkv, bk, nullptr, (__half*)pKh, 4, bv, (__half*)pVth);

    tilesum_kernel<<<B_ * H_ * NT_, 64>>>();
    scan_kernel<<<(B_ * H_ * E_) / 256, 256>>>();

    // per-batch scores -> softmax on L2-resident scratch
    for (int b = 0; b < B_; b++) {
        scores_mma_kernel<<<dim3(NT_, NT_, H_), 128>>>(b);
        softmax_h_kernel<<<dim3(S_ / 256, S_, 1), 256>>>(b);
    }

    // attn @ V: single full-parallelism launch
    attnv_mma_kernel<<<dim3(NT_, B_ * H_), 128>>>();

    // output projection: plain K=1024
    gemm_mma_kernel<<<dim3(8, 64), 128, SMEM_G>>>(
        (__half*)pAOh, (__half*)pWo, bo, out, nullptr, 0, nullptr, nullptr);
}

// round 14
// speedup vs baseline: 1.1920x; 1.1920x over previous
#include <cuda_runtime.h>
#include <cuda_fp16.h>
#include <cstdint>
#include <math.h>

#define B_  8
#define S_  1024
#define D_  1024
#define H_  16
#define E_  64
#define HE_ 1024
#define BS_ (B_*S_)
#define NT_ (S_/64)

// ---------------- scratch (device globals; no runtime allocation) ----------
__device__ float g_Sc[(size_t)H_*S_*S_];   // per-batch score scratch (L2-resident)
__device__ float g_TS[B_*H_*NT_*E_];
__device__ float g_P [B_*H_*(NT_+1)*E_];

// fp16 operands
__device__ __half g_X1h[(size_t)BS_*D_];
__device__ __half g_X2h[(size_t)BS_*D_];
__device__ __half g_AOh[(size_t)BS_*D_];       // attention output, fp16 hi
__device__ __half g_Wq [(size_t)HE_*D_];       // [N,K] K-major
__device__ __half g_Wkv[(size_t)2*HE_*D_];     // [2048,K]: rows 0..1023 Wk, 1024..2047 Wv
__device__ __half g_Wo [(size_t)HE_*D_];

// per-head fp16 operands for attention mma
__device__ __half g_Qh[(size_t)B_*H_*S_*E_];   // [bh][s][e]
__device__ __half g_Kh[(size_t)B_*H_*S_*E_];   // [bh][s][e]
__device__ __half g_Vth[(size_t)B_*H_*E_*S_];  // [bh][e][s]
__device__ __half g_Ah[(size_t)B_*H_*S_*S_];   // [bh][q][k] (hi only)

// ---------------- PTX helpers (baseline sm_80+) -----------------------------
__device__ __forceinline__ uint32_t smem_u32(const void* p) {
    uint32_t a;
    asm("{ .reg .u64 t; cvta.to.shared.u64 t, %1; cvt.u32.u64 %0, t; }" : "=r"(a) : "l"(p));
    return a;
}
__device__ __forceinline__ void cp16(uint32_t s, const void* g) {
    asm volatile("cp.async.cg.shared.global [%0], [%1], 16;" :: "r"(s), "l"(g));
}
#define CP_COMMIT() asm volatile("cp.async.commit_group;" ::: "memory")
#define CP_WAIT1()  asm volatile("cp.async.wait_group 1;" ::: "memory")
#define CP_WAIT0()  asm volatile("cp.async.wait_group 0;" ::: "memory")

#define LDSM4(r, a) \
    asm volatile("ldmatrix.sync.aligned.m8n8.x4.shared.b16 {%0,%1,%2,%3}, [%4];" \
        : "=r"((r)[0]), "=r"((r)[1]), "=r"((r)[2]), "=r"((r)[3]) : "r"(a))

#define MMAF16(c, a, b0v, b1v) \
    asm volatile("mma.sync.aligned.m16n8k16.row.col.f32.f16.f16.f32 " \
        "{%0,%1,%2,%3}, {%4,%5,%6,%7}, {%8,%9}, {%0,%1,%2,%3};" \
        : "+f"((c)[0]), "+f"((c)[1]), "+f"((c)[2]), "+f"((c)[3]) \
        : "r"((a)[0]), "r"((a)[1]), "r"((a)[2]), "r"((a)[3]), "r"(b0v), "r"(b1v))

// ---------------- pack kernels ---------------------------------------------
__global__ __launch_bounds__(256) void cvt_h_kernel(
    const float* __restrict__ in, __half* __restrict__ out, int n4)
{
    int i = blockIdx.x * 256 + threadIdx.x;
    if (i >= n4) return;
    float4 v = ((const float4*)in)[i];
    *(__half2*)(out + i*4)     = __half2(__float2half_rn(v.x), __float2half_rn(v.y));
    *(__half2*)(out + i*4 + 2) = __half2(__float2half_rn(v.z), __float2half_rn(v.w));
}

// W fp32 [K=1024, N=1024] -> Wt fp16 [N, 1024] K-major
__global__ __launch_bounds__(256) void pack_w_kernel(
    const float* __restrict__ W, __half* __restrict__ out)
{
    __shared__ float t[32][33];
    const int n0 = blockIdx.x * 32, k0 = blockIdx.y * 32;
    const int tx = threadIdx.x, ty = threadIdx.y;
    #pragma unroll
    for (int i = 0; i < 4; i++)
        t[ty + i*8][tx] = W[(size_t)(k0 + ty + i*8) * 1024 + n0 + tx];
    __syncthreads();
    #pragma unroll
    for (int i = 0; i < 4; i++)
        out[(size_t)(n0 + ty + i*8) * 1024 + k0 + tx] = __float2half_rn(t[tx][ty + i*8]);
}

// ---------------- GEMM (mma.sync fp16, K=1024, 8 warps x 64x32) ------------
// modes: 0 = fp32 C row-major; 2 = per-head fp16 hi; 3 = per-head fp16 TRANSPOSED;
//        4 = fused KV: blockIdx.x<8 -> K (mode2, Oh/bias); else V (mode3, Oh2/bias2)
__global__ __launch_bounds__(256) void gemm_mma_kernel(
    const __half* __restrict__ Ap, const __half* __restrict__ Bp,
    const float* __restrict__ bias, float* __restrict__ C,
    __half* __restrict__ Oh, int mode,
    const float* __restrict__ bias2, __half* __restrict__ Oh2)
{
    extern __shared__ char smch[];
    const uint32_t sb = smem_u32(smch);
    const int tid = threadIdx.x;
    const int lane = tid & 31, wid = tid >> 5;
    const int wm = wid >> 2, wn = wid & 3;
    const size_t m0 = (size_t)blockIdx.y * 128;
    const size_t n0 = (size_t)blockIdx.x * 128;

    const int lr = tid >> 2;
    const int lco = (tid & 3) * 16;
    const __half* gA0 = Ap + (m0 + lr) * D_ + (tid & 3) * 8;
    const __half* gB0 = Bp + (n0 + lr) * D_ + (tid & 3) * 8;
    const uint32_t smA = sb + lr * 80 + lco;
    const uint32_t smB = smA + 10240;

    float acc[4][4][4];
    #pragma unroll
    for (int a = 0; a < 4; a++)
        #pragma unroll
        for (int b = 0; b < 4; b++)
            #pragma unroll
            for (int c = 0; c < 4; c++) acc[a][b][c] = 0.f;

    #define LOADST(kt, st) do {                                        \
        const uint32_t so_ = (uint32_t)(st) * 20480u;                  \
        const __half* ga_ = gA0 + (size_t)(kt) * 32;                   \
        const __half* gb_ = gB0 + (size_t)(kt) * 32;                   \
        cp16(smA + so_,           ga_);                                \
        cp16(smA + so_ + 64*80,   ga_ + (size_t)64 * D_);              \
        cp16(smB + so_,           gb_);                                \
        cp16(smB + so_ + 64*80,   gb_ + (size_t)64 * D_);              \
        CP_COMMIT();                                                   \
    } while (0)

    LOADST(0, 0);
    LOADST(1, 1);

    const uint32_t aAddr = sb + (uint32_t)(wm*64 + (lane & 15)) * 80 + ((lane >> 4) << 4);
    const uint32_t bAddr = sb + 10240 +
        (uint32_t)(wn*32 + ((lane >> 3) & 1) * 8 + (lane & 7)) * 80 + ((lane >> 4) << 4);

    const int NKT = D_ / 32;   // 32
    #pragma unroll 1
    for (int kt = 0; kt < NKT; kt++) {
        const int st = kt % 3;
        CP_WAIT1();
        __syncthreads();
        if (kt + 2 < NKT) LOADST(kt + 2, (kt + 2) % 3);
        const uint32_t so = (uint32_t)st * 20480u;
        #pragma unroll
        for (int ks = 0; ks < 2; ks++) {
            uint32_t afr[4][4], bfr[2][4];
            #pragma unroll
            for (int mt = 0; mt < 4; mt++)
                LDSM4(afr[mt], aAddr + so + (uint32_t)mt*16*80 + ks*32);
            #pragma unroll
            for (int nt2 = 0; nt2 < 2; nt2++)
                LDSM4(bfr[nt2], bAddr + so + (uint32_t)nt2*16*80 + ks*32);
            #pragma unroll
            for (int mt = 0; mt < 4; mt++)
                #pragma unroll
                for (int nt = 0; nt < 4; nt++)
                    MMAF16(acc[mt][nt], afr[mt],
                           bfr[nt >> 1][nt & 1], bfr[nt >> 1][2 + (nt & 1)]);
        }
    }
    CP_WAIT0();

    const int crow = lane >> 2, ccol = (lane & 3) * 2;
    int emode = mode;
    const float* bb = bias;
    __half* oo = Oh;
    int nsub = 0;
    if (mode == 4) {
        if (blockIdx.x < 8) { emode = 2; }
        else { emode = 3; bb = bias2; oo = Oh2; nsub = 1024; }
    }

    if (emode == 0) {
        #pragma unroll
        for (int nt = 0; nt < 4; nt++) {
            const int n = (int)n0 + wn*32 + nt*8 + ccol;
            const float b0v = bb[n], b1v = bb[n + 1];
            #pragma unroll
            for (int mt = 0; mt < 4; mt++) {
                const size_t m = m0 + wm*64 + mt*16 + crow;
                float2 v0, v1;
                v0.x = acc[mt][nt][0] + b0v; v0.y = acc[mt][nt][1] + b1v;
                v1.x = acc[mt][nt][2] + b0v; v1.y = acc[mt][nt][3] + b1v;
                *(float2*)(C + m * 1024 + n)       = v0;
                *(float2*)(C + (m + 8) * 1024 + n) = v1;
            }
        }
    } else if (emode == 2) {
        #pragma unroll
        for (int nt = 0; nt < 4; nt++) {
            const int n = (int)n0 + wn*32 + nt*8 + ccol;
            const float b0v = bb[n], b1v = bb[n + 1];
            const int h = n >> 6, e = n & 63;
            #pragma unroll
            for (int mt = 0; mt < 4; mt++) {
                #pragma unroll
                for (int half = 0; half < 2; half++) {
                    const size_t m = m0 + wm*64 + mt*16 + crow + half*8;
                    const int b2 = (int)(m >> 10), s = (int)(m & 1023);
                    const size_t o = (((size_t)(b2*16 + h) * 1024 + s) * 64 + e);
                    *(__half2*)(oo + o) = __half2(
                        __float2half_rn(acc[mt][nt][half*2]     + b0v),
                        __float2half_rn(acc[mt][nt][half*2 + 1] + b1v));
                }
            }
        }
    } else {   // emode 3: transposed per-head [bh][e][s]
        #pragma unroll
        for (int nt = 0; nt < 4; nt++) {
            const int ng = (int)n0 + wn*32 + nt*8 + ccol;
            const int n = ng - nsub;
            const float b0v = bb[n], b1v = bb[n + 1];
            const int h = n >> 6, e = n & 63;
            #pragma unroll
            for (int mt = 0; mt < 4; mt++) {
                #pragma unroll
                for (int half = 0; half < 2; half++) {
                    const size_t m = m0 + wm*64 + mt*16 + crow + half*8;
                    const int b2 = (int)(m >> 10), s = (int)(m & 1023);
                    const size_t o0 = (((size_t)(b2*16 + h) * 64 + e)     << 10) + s;
                    const size_t o1 = (((size_t)(b2*16 + h) * 64 + e + 1) << 10) + s;
                    oo[o0] = __float2half_rn(acc[mt][nt][half*2]     + b0v);
                    oo[o1] = __float2half_rn(acc[mt][nt][half*2 + 1] + b1v);
                }
            }
        }
    }
    #undef LOADST
}

// ---------------- scores via mma (hi-only), quirks fused, per-batch --------
__global__ __launch_bounds__(128) void scores_mma_kernel(int b)
{
    const int kt = blockIdx.x, qt = blockIdx.y;
    if (kt > qt) return;
    const int h = blockIdx.z;
    const int bh = b * 16 + h;

    __shared__ __align__(16) char sm[2 * 64 * 144];
    const uint32_t sQH = smem_u32(sm);
    const uint32_t sKH = sQH + 9216;

    const int tid = threadIdx.x;
    const int lane = tid & 31, wid = tid >> 5;
    const int wm = wid >> 1, wn = wid & 1;

    const __half* gQH = g_Qh + ((size_t)bh * 1024 + qt*64) * 64;
    const __half* gKH = g_Kh + ((size_t)bh * 1024 + kt*64) * 64;
    #pragma unroll
    for (int i = tid; i < 512; i += 128) {
        const int r = i >> 3, c = i & 7;
        const size_t go = (size_t)r * 64 + c * 8;
        const uint32_t so = r * 144 + c * 16;
        *(uint4*)(sm + so)        = *(const uint4*)(gQH + go);
        *(uint4*)(sm + 9216 + so) = *(const uint4*)(gKH + go);
    }
    __syncthreads();

    float acc[2][4][4];
    #pragma unroll
    for (int a = 0; a < 2; a++)
        #pragma unroll
        for (int b2 = 0; b2 < 4; b2++)
            #pragma unroll
            for (int c = 0; c < 4; c++) acc[a][b2][c] = 0.f;

    const uint32_t aOff = (uint32_t)(wm*32 + (lane & 15)) * 144 + ((lane >> 4) << 4);
    const uint32_t bOff = (uint32_t)(wn*32 + ((lane >> 3) & 1)*8 + (lane & 7)) * 144 + ((lane >> 4) << 4);

    #pragma unroll
    for (int es = 0; es < 4; es++) {
        const uint32_t cb = es * 32;
        uint32_t ah[2][4], bh2[2][4];
        #pragma unroll
        for (int mt = 0; mt < 2; mt++)
            LDSM4(ah[mt], sQH + aOff + (uint32_t)mt*16*144 + cb);
        #pragma unroll
        for (int nt2 = 0; nt2 < 2; nt2++)
            LDSM4(bh2[nt2], sKH + bOff + (uint32_t)nt2*16*144 + cb);
        #pragma unroll
        for (int mt = 0; mt < 2; mt++)
            #pragma unroll
            for (int nt = 0; nt < 4; nt++)
                MMAF16(acc[mt][nt], ah[mt], bh2[nt>>1][nt&1], bh2[nt>>1][2+(nt&1)]);
    }

    const float scale = 0.35355339059327373f;  // 1/sqrt(8) batch-size quirk
    float* out = g_Sc + (size_t)h * S_ * S_;
    #pragma unroll
    for (int mt = 0; mt < 2; mt++) {
        #pragma unroll
        for (int half = 0; half < 2; half++) {
            const int q = qt*64 + wm*32 + mt*16 + (lane >> 2) + half*8;
            #pragma unroll
            for (int nt = 0; nt < 4; nt++) {
                const int k0 = kt*64 + wn*32 + nt*8 + (lane & 3)*2;
                float v0 = acc[mt][nt][half*2]     * scale;
                float v1 = acc[mt][nt][half*2 + 1] * scale;
                if (k0     > q || v0 == 0.0f) v0 = -1e9f;
                if (k0 + 1 > q || v1 == 0.0f) v1 = -1e9f;
                *(float2*)(out + (size_t)q * S_ + k0) = make_float2(v0, v1);
            }
        }
    }
}

// ---------------- softmax over heads -> fp16 attn (hi only), per-batch -----
__global__ void softmax_h_kernel(int b)
{
    const int k = blockIdx.x * 256 + threadIdx.x;
    const int q = blockIdx.y;
    const int kmax = ((q >> 6) + 1) << 6;
    if (k >= kmax) return;

    const size_t so = (size_t)q * S_ + k;
    const size_t hs = (size_t)S_ * S_;
    float s[H_];
    float m = -3.4e38f;
    #pragma unroll
    for (int h = 0; h < H_; h++) { s[h] = g_Sc[so + h * hs]; m = fmaxf(m, s[h]); }
    float Z = 0.f;
    #pragma unroll
    for (int h = 0; h < H_; h++) { s[h] = expf(s[h] - m); Z += s[h]; }
    const float inv = 1.0f / Z;
    const size_t ab = (size_t)b * H_ * S_ * S_ + so;
    #pragma unroll
    for (int h = 0; h < H_; h++)
        g_Ah[ab + h * hs] = __float2half_rn(s[h] * inv);
}

// ---------------- V tile sums (from transposed fp16 V) + prefix scan -------
__global__ void tilesum_kernel()
{
    const int blk = blockIdx.x;
    const int e = threadIdx.x;
    const int tt = blk & (NT_ - 1);
    const int bh = blk / NT_;
    const __half2* Vb = (const __half2*)(g_Vth + (((size_t)bh * 64 + e) << 10) + tt*64);
    float sum = 0.f;
    #pragma unroll
    for (int k = 0; k < 32; k++) {
        const __half2 v = Vb[k];
        sum += __half2float(v.x) + __half2float(v.y);
    }
    g_TS[((size_t)bh * NT_ + tt) * E_ + e] = sum;
}

__global__ void scan_kernel()
{
    const int id = blockIdx.x * 256 + threadIdx.x;
    const int e = id & 63, bh = id >> 6;
    float* P = g_P + (size_t)bh * (NT_ + 1) * E_;
    float p = 0.f;
    P[e] = 0.f;
    #pragma unroll
    for (int tt = 0; tt < NT_; tt++) {
        p += g_TS[((size_t)bh * NT_ + tt) * E_ + e];
        P[(tt + 1) * E_ + e] = p;
    }
}

// ---------------- attn @ V via mma + masked suffix (single launch) ---------
__global__ __launch_bounds__(128) void attnv_mma_kernel()
{
    const int qt = blockIdx.x, bh = blockIdx.y;
    const int b = bh >> 4, h = bh & 15;

    __shared__ __align__(16) char sm[2 * 64 * 144];
    const uint32_t sAH = smem_u32(sm);
    const uint32_t sVH = sAH + 9216;

    const int tid = threadIdx.x;
    const int lane = tid & 31, wid = tid >> 5;
    const int wm = wid >> 1, wn = wid & 1;

    float acc[2][4][4];
    #pragma unroll
    for (int a = 0; a < 2; a++)
        #pragma unroll
        for (int b2 = 0; b2 < 4; b2++)
            #pragma unroll
            for (int c = 0; c < 4; c++) acc[a][b2][c] = 0.f;

    const uint32_t aOff = (uint32_t)(wm*32 + (lane & 15)) * 144 + ((lane >> 4) << 4);
    const uint32_t bOff = (uint32_t)(wn*32 + ((lane >> 3) & 1)*8 + (lane & 7)) * 144 + ((lane >> 4) << 4);

    const __half* gAH0 = g_Ah + ((size_t)bh * 1024 + qt*64) * 1024;
    const __half* gVH0 = g_Vth + (size_t)bh * 64 * 1024;

    for (int kt = 0; kt <= qt; kt++) {
        __syncthreads();
        #pragma unroll
        for (int i = tid; i < 512; i += 128) {
            const int r = i >> 3, c = i & 7;
            const size_t go = (size_t)r * 1024 + kt*64 + c * 8;
            const uint32_t so = r * 144 + c * 16;
            *(uint4*)(sm + so)        = *(const uint4*)(gAH0 + go);
            *(uint4*)(sm + 9216 + so) = *(const uint4*)(gVH0 + go);
        }
        __syncthreads();

        #pragma unroll
        for (int ks = 0; ks < 4; ks++) {
            const uint32_t cb = ks * 32;
            uint32_t ah[2][4], vh[2][4];
            #pragma unroll
            for (int mt = 0; mt < 2; mt++)
                LDSM4(ah[mt], sAH + aOff + (uint32_t)mt*16*144 + cb);
            #pragma unroll
            for (int nt2 = 0; nt2 < 2; nt2++)
                LDSM4(vh[nt2], sVH + bOff + (uint32_t)nt2*16*144 + cb);
            #pragma unroll
            for (int mt = 0; mt < 2; mt++)
                #pragma unroll
                for (int nt = 0; nt < 4; nt++)
                    MMAF16(acc[mt][nt], ah[mt], vh[nt>>1][nt&1], vh[nt>>1][2+(nt&1)]);
        }
    }

    const float* P = g_P + (size_t)bh * (NT_ + 1) * E_;
    #pragma unroll
    for (int nt = 0; nt < 4; nt++) {
        const int e0 = wn*32 + nt*8 + (lane & 3)*2;
        const float s0 = (P[NT_*E_ + e0]     - P[(qt+1)*E_ + e0])     * 0.0625f;
        const float s1 = (P[NT_*E_ + e0 + 1] - P[(qt+1)*E_ + e0 + 1]) * 0.0625f;
        #pragma unroll
        for (int mt = 0; mt < 2; mt++) {
            #pragma unroll
            for (int half = 0; half < 2; half++) {
                const int q = wm*32 + mt*16 + (lane >> 2) + half*8;
                __half* base = g_AOh + ((size_t)(b*1024 + qt*64 + q)) * D_ + h*64 + e0;
                *(__half2*)(base) = __half2(
                    __float2half_rn(acc[mt][nt][half*2]     + s0),
                    __float2half_rn(acc[mt][nt][half*2 + 1] + s1));
            }
        }
    }
}

// ---------------- launch ---------------------------------------------------
extern "C" void kernel_launch(void* const* d_in, const int* in_sizes, int n_in,
                              void* d_out, int out_size)
{
    const float* X1 = (const float*)d_in[0];
    const float* X2 = (const float*)d_in[1];
    const float* Wq = (const float*)d_in[2];
    const float* bq = (const float*)d_in[3];
    const float* Wk = (const float*)d_in[4];
    const float* bk = (const float*)d_in[5];
    const float* Wv = (const float*)d_in[6];
    const float* bv = (const float*)d_in[7];
    const float* Wo = (const float*)d_in[8];
    const float* bo = (const float*)d_in[9];
    float* out = (float*)d_out;

    void *pX1h, *pX2h, *pAOh, *pWq, *pWkv, *pWo;
    void *pQh, *pKh, *pVth;
    cudaGetSymbolAddress(&pX1h, g_X1h); cudaGetSymbolAddress(&pX2h, g_X2h);
    cudaGetSymbolAddress(&pAOh, g_AOh);
    cudaGetSymbolAddress(&pWq, g_Wq); cudaGetSymbolAddress(&pWkv, g_Wkv);
    cudaGetSymbolAddress(&pWo, g_Wo);
    cudaGetSymbolAddress(&pQh, g_Qh); cudaGetSymbolAddress(&pKh, g_Kh);
    cudaGetSymbolAddress(&pVth, g_Vth);

    const uint32_t SMEM_G = 61440;
    cudaFuncSetAttribute(gemm_mma_kernel,
                         cudaFuncAttributeMaxDynamicSharedMemorySize, SMEM_G);

    const int n4x = BS_ * D_ / 4;
    cvt_h_kernel<<<n4x / 256, 256>>>(X1, (__half*)pX1h, n4x);
    cvt_h_kernel<<<n4x / 256, 256>>>(X2, (__half*)pX2h, n4x);

    const dim3 gT(32, 32), bT(32, 8);
    pack_w_kernel<<<gT, bT>>>(Wq, (__half*)pWq);
    pack_w_kernel<<<gT, bT>>>(Wk, (__half*)pWkv);
    pack_w_kernel<<<gT, bT>>>(Wv, (__half*)pWkv + (size_t)1024*1024);
    pack_w_kernel<<<gT, bT>>>(Wo, (__half*)pWo);

    // Q projection -> per-head fp16 hi (8-warp proven GEMM)
    gemm_mma_kernel<<<dim3(8, 64), 256, SMEM_G>>>(
        (__half*)pX1h, (__half*)pWq, bq, nullptr, (__half*)pQh, 2, nullptr, nullptr);
    // fused K+V projection: nb<8 -> Kh (mode2), nb>=8 -> Vth transposed (mode3)
    gemm_mma_kernel<<<dim3(16, 64), 256, SMEM_G>>>(
        (__half*)pX2h, (__half*)pWkv, bk, nullptr, (__half*)pKh, 4, bv, (__half*)pVth);

    tilesum_kernel<<<B_ * H_ * NT_, 64>>>();
    scan_kernel<<<(B_ * H_ * E_) / 256, 256>>>();

    // per-batch scores -> softmax on L2-resident scratch
    for (int b = 0; b < B_; b++) {
        scores_mma_kernel<<<dim3(NT_, NT_, H_), 128>>>(b);
        softmax_h_kernel<<<dim3(S_ / 256, S_, 1), 256>>>(b);
    }

    // attn @ V: single full-parallelism launch
    attnv_mma_kernel<<<dim3(NT_, B_ * H_), 128>>>();

    // output projection: plain K=1024
    gemm_mma_kernel<<<dim3(8, 64), 256, SMEM_G>>>(
        (__half*)pAOh, (__half*)pWo, bo, out, nullptr, 0, nullptr, nullptr);
}

// round 15
// speedup vs baseline: 1.2164x; 1.0204x over previous
#include <cuda_runtime.h>
#include <cuda_fp16.h>
#include <cstdint>
#include <math.h>

#define B_  8
#define S_  1024
#define D_  1024
#define H_  16
#define E_  64
#define HE_ 1024
#define BS_ (B_*S_)
#define NT_ (S_/64)

// ---------------- scratch (device globals; no runtime allocation) ----------
__device__ float g_Sc[(size_t)H_*S_*S_];   // per-batch score scratch (L2-resident)
__device__ float g_TS[B_*H_*NT_*E_];
__device__ float g_P [B_*H_*(NT_+1)*E_];

// fp16 operands
__device__ __half g_X1h[(size_t)BS_*D_];
__device__ __half g_X2h[(size_t)BS_*D_];
__device__ __half g_AOh[(size_t)BS_*D_];        // attention output, fp16 hi
__device__ __half g_Wqkv[(size_t)3*HE_*D_];     // [3072,K]: Wq | Wk | Wv (K-major)
__device__ __half g_Wo [(size_t)HE_*D_];

// per-head fp16 operands for attention mma
__device__ __half g_Qh[(size_t)B_*H_*S_*E_];   // [bh][s][e]
__device__ __half g_Kh[(size_t)B_*H_*S_*E_];   // [bh][s][e]
__device__ __half g_Vth[(size_t)B_*H_*E_*S_];  // [bh][e][s]
__device__ __half g_Ah[(size_t)B_*H_*S_*S_];   // [bh][q][k] (hi only)

// ---------------- PTX helpers (baseline sm_80+) -----------------------------
__device__ __forceinline__ uint32_t smem_u32(const void* p) {
    uint32_t a;
    asm("{ .reg .u64 t; cvta.to.shared.u64 t, %1; cvt.u32.u64 %0, t; }" : "=r"(a) : "l"(p));
    return a;
}
__device__ __forceinline__ void cp16(uint32_t s, const void* g) {
    asm volatile("cp.async.cg.shared.global [%0], [%1], 16;" :: "r"(s), "l"(g));
}
#define CP_COMMIT() asm volatile("cp.async.commit_group;" ::: "memory")
#define CP_WAIT1()  asm volatile("cp.async.wait_group 1;" ::: "memory")
#define CP_WAIT0()  asm volatile("cp.async.wait_group 0;" ::: "memory")

#define LDSM4(r, a) \
    asm volatile("ldmatrix.sync.aligned.m8n8.x4.shared.b16 {%0,%1,%2,%3}, [%4];" \
        : "=r"((r)[0]), "=r"((r)[1]), "=r"((r)[2]), "=r"((r)[3]) : "r"(a))

#define MMAF16(c, a, b0v, b1v) \
    asm volatile("mma.sync.aligned.m16n8k16.row.col.f32.f16.f16.f32 " \
        "{%0,%1,%2,%3}, {%4,%5,%6,%7}, {%8,%9}, {%0,%1,%2,%3};" \
        : "+f"((c)[0]), "+f"((c)[1]), "+f"((c)[2]), "+f"((c)[3]) \
        : "r"((a)[0]), "r"((a)[1]), "r"((a)[2]), "r"((a)[3]), "r"(b0v), "r"(b1v))

// ---------------- pack kernels ---------------------------------------------
__global__ __launch_bounds__(256) void cvt_h_kernel(
    const float* __restrict__ in, __half* __restrict__ out, int n4)
{
    int i = blockIdx.x * 256 + threadIdx.x;
    if (i >= n4) return;
    float4 v = ((const float4*)in)[i];
    *(__half2*)(out + i*4)     = __half2(__float2half_rn(v.x), __float2half_rn(v.y));
    *(__half2*)(out + i*4 + 2) = __half2(__float2half_rn(v.z), __float2half_rn(v.w));
}

// W fp32 [K=1024, N=1024] -> Wt fp16 [N, 1024] K-major
__global__ __launch_bounds__(256) void pack_w_kernel(
    const float* __restrict__ W, __half* __restrict__ out)
{
    __shared__ float t[32][33];
    const int n0 = blockIdx.x * 32, k0 = blockIdx.y * 32;
    const int tx = threadIdx.x, ty = threadIdx.y;
    #pragma unroll
    for (int i = 0; i < 4; i++)
        t[ty + i*8][tx] = W[(size_t)(k0 + ty + i*8) * 1024 + n0 + tx];
    __syncthreads();
    #pragma unroll
    for (int i = 0; i < 4; i++)
        out[(size_t)(n0 + ty + i*8) * 1024 + k0 + tx] = __float2half_rn(t[tx][ty + i*8]);
}

// ---------------- GEMM (mma.sync fp16, K=1024, 8 warps x 64x32) ------------
// modes: 0 = fp32 C row-major;
//        5 = fused QKV: bx<8 -> Q (A=Ap, Oh, bias); bx<16 -> K (A=Ap2, Oh2, bias2);
//            else -> V transposed (A=Ap2, Oh3, bias3)
__global__ __launch_bounds__(256) void gemm_mma_kernel(
    const __half* __restrict__ Ap, const __half* __restrict__ Ap2,
    const __half* __restrict__ Bp,
    const float* __restrict__ bias, const float* __restrict__ bias2,
    const float* __restrict__ bias3,
    float* __restrict__ C,
    __half* __restrict__ Oh, __half* __restrict__ Oh2, __half* __restrict__ Oh3,
    int mode)
{
    extern __shared__ char smch[];
    const uint32_t sb = smem_u32(smch);
    const int tid = threadIdx.x;
    const int lane = tid & 31, wid = tid >> 5;
    const int wm = wid >> 2, wn = wid & 3;
    const int bx = blockIdx.x;
    const size_t m0 = (size_t)blockIdx.y * 128;
    const size_t n0 = (size_t)bx * 128;

    // per-block dispatch
    int emode;
    const __half* Asel;
    const float* bb;
    __half* oo;
    int nsub;
    if (mode == 0) {
        emode = 0; Asel = Ap; bb = bias; oo = Oh; nsub = 0;
    } else {
        if (bx < 8)       { emode = 2; Asel = Ap;  bb = bias;  oo = Oh;  nsub = 0; }
        else if (bx < 16) { emode = 2; Asel = Ap2; bb = bias2; oo = Oh2; nsub = 1024; }
        else              { emode = 3; Asel = Ap2; bb = bias3; oo = Oh3; nsub = 2048; }
    }

    const int lr = tid >> 2;
    const int lco = (tid & 3) * 16;
    const __half* gA0 = Asel + (m0 + lr) * D_ + (tid & 3) * 8;
    const __half* gB0 = Bp + (n0 + lr) * D_ + (tid & 3) * 8;
    const uint32_t smA = sb + lr * 80 + lco;
    const uint32_t smB = smA + 10240;

    float acc[4][4][4];
    #pragma unroll
    for (int a = 0; a < 4; a++)
        #pragma unroll
        for (int b = 0; b < 4; b++)
            #pragma unroll
            for (int c = 0; c < 4; c++) acc[a][b][c] = 0.f;

    #define LOADST(kt, st) do {                                        \
        const uint32_t so_ = (uint32_t)(st) * 20480u;                  \
        const __half* ga_ = gA0 + (size_t)(kt) * 32;                   \
        const __half* gb_ = gB0 + (size_t)(kt) * 32;                   \
        cp16(smA + so_,           ga_);                                \
        cp16(smA + so_ + 64*80,   ga_ + (size_t)64 * D_);              \
        cp16(smB + so_,           gb_);                                \
        cp16(smB + so_ + 64*80,   gb_ + (size_t)64 * D_);              \
        CP_COMMIT();                                                   \
    } while (0)

    LOADST(0, 0);
    LOADST(1, 1);

    const uint32_t aAddr = sb + (uint32_t)(wm*64 + (lane & 15)) * 80 + ((lane >> 4) << 4);
    const uint32_t bAddr = sb + 10240 +
        (uint32_t)(wn*32 + ((lane >> 3) & 1) * 8 + (lane & 7)) * 80 + ((lane >> 4) << 4);

    const int NKT = D_ / 32;   // 32
    #pragma unroll 1
    for (int kt = 0; kt < NKT; kt++) {
        const int st = kt % 3;
        CP_WAIT1();
        __syncthreads();
        if (kt + 2 < NKT) LOADST(kt + 2, (kt + 2) % 3);
        const uint32_t so = (uint32_t)st * 20480u;
        #pragma unroll
        for (int ks = 0; ks < 2; ks++) {
            uint32_t afr[4][4], bfr[2][4];
            #pragma unroll
            for (int mt = 0; mt < 4; mt++)
                LDSM4(afr[mt], aAddr + so + (uint32_t)mt*16*80 + ks*32);
            #pragma unroll
            for (int nt2 = 0; nt2 < 2; nt2++)
                LDSM4(bfr[nt2], bAddr + so + (uint32_t)nt2*16*80 + ks*32);
            #pragma unroll
            for (int mt = 0; mt < 4; mt++)
                #pragma unroll
                for (int nt = 0; nt < 4; nt++)
                    MMAF16(acc[mt][nt], afr[mt],
                           bfr[nt >> 1][nt & 1], bfr[nt >> 1][2 + (nt & 1)]);
        }
    }
    CP_WAIT0();

    const int crow = lane >> 2, ccol = (lane & 3) * 2;

    if (emode == 0) {
        #pragma unroll
        for (int nt = 0; nt < 4; nt++) {
            const int n = (int)n0 + wn*32 + nt*8 + ccol;
            const float b0v = bb[n], b1v = bb[n + 1];
            #pragma unroll
            for (int mt = 0; mt < 4; mt++) {
                const size_t m = m0 + wm*64 + mt*16 + crow;
                float2 v0, v1;
                v0.x = acc[mt][nt][0] + b0v; v0.y = acc[mt][nt][1] + b1v;
                v1.x = acc[mt][nt][2] + b0v; v1.y = acc[mt][nt][3] + b1v;
                *(float2*)(C + m * 1024 + n)       = v0;
                *(float2*)(C + (m + 8) * 1024 + n) = v1;
            }
        }
    } else if (emode == 2) {
        #pragma unroll
        for (int nt = 0; nt < 4; nt++) {
            const int n = (int)n0 + wn*32 + nt*8 + ccol - nsub;
            const float b0v = bb[n], b1v = bb[n + 1];
            const int h = n >> 6, e = n & 63;
            #pragma unroll
            for (int mt = 0; mt < 4; mt++) {
                #pragma unroll
                for (int half = 0; half < 2; half++) {
                    const size_t m = m0 + wm*64 + mt*16 + crow + half*8;
                    const int b2 = (int)(m >> 10), s = (int)(m & 1023);
                    const size_t o = (((size_t)(b2*16 + h) * 1024 + s) * 64 + e);
                    *(__half2*)(oo + o) = __half2(
                        __float2half_rn(acc[mt][nt][half*2]     + b0v),
                        __float2half_rn(acc[mt][nt][half*2 + 1] + b1v));
                }
            }
        }
    } else {   // emode 3: transposed per-head [bh][e][s]
        #pragma unroll
        for (int nt = 0; nt < 4; nt++) {
            const int n = (int)n0 + wn*32 + nt*8 + ccol - nsub;
            const float b0v = bb[n], b1v = bb[n + 1];
            const int h = n >> 6, e = n & 63;
            #pragma unroll
            for (int mt = 0; mt < 4; mt++) {
                #pragma unroll
                for (int half = 0; half < 2; half++) {
                    const size_t m = m0 + wm*64 + mt*16 + crow + half*8;
                    const int b2 = (int)(m >> 10), s = (int)(m & 1023);
                    const size_t o0 = (((size_t)(b2*16 + h) * 64 + e)     << 10) + s;
                    const size_t o1 = (((size_t)(b2*16 + h) * 64 + e + 1) << 10) + s;
                    oo[o0] = __float2half_rn(acc[mt][nt][half*2]     + b0v);
                    oo[o1] = __float2half_rn(acc[mt][nt][half*2 + 1] + b1v);
                }
            }
        }
    }
    #undef LOADST
}

// ---------------- scores via mma (hi-only), quirks fused, per-batch --------
__global__ __launch_bounds__(128) void scores_mma_kernel(int b)
{
    const int kt = blockIdx.x, qt = blockIdx.y;
    if (kt > qt) return;
    const int h = blockIdx.z;
    const int bh = b * 16 + h;

    __shared__ __align__(16) char sm[2 * 64 * 144];
    const uint32_t sQH = smem_u32(sm);
    const uint32_t sKH = sQH + 9216;

    const int tid = threadIdx.x;
    const int lane = tid & 31, wid = tid >> 5;
    const int wm = wid >> 1, wn = wid & 1;

    const __half* gQH = g_Qh + ((size_t)bh * 1024 + qt*64) * 64;
    const __half* gKH = g_Kh + ((size_t)bh * 1024 + kt*64) * 64;
    #pragma unroll
    for (int i = tid; i < 512; i += 128) {
        const int r = i >> 3, c = i & 7;
        const size_t go = (size_t)r * 64 + c * 8;
        const uint32_t so = r * 144 + c * 16;
        *(uint4*)(sm + so)        = *(const uint4*)(gQH + go);
        *(uint4*)(sm + 9216 + so) = *(const uint4*)(gKH + go);
    }
    __syncthreads();

    float acc[2][4][4];
    #pragma unroll
    for (int a = 0; a < 2; a++)
        #pragma unroll
        for (int b2 = 0; b2 < 4; b2++)
            #pragma unroll
            for (int c = 0; c < 4; c++) acc[a][b2][c] = 0.f;

    const uint32_t aOff = (uint32_t)(wm*32 + (lane & 15)) * 144 + ((lane >> 4) << 4);
    const uint32_t bOff = (uint32_t)(wn*32 + ((lane >> 3) & 1)*8 + (lane & 7)) * 144 + ((lane >> 4) << 4);

    #pragma unroll
    for (int es = 0; es < 4; es++) {
        const uint32_t cb = es * 32;
        uint32_t ah[2][4], bh2[2][4];
        #pragma unroll
        for (int mt = 0; mt < 2; mt++)
            LDSM4(ah[mt], sQH + aOff + (uint32_t)mt*16*144 + cb);
        #pragma unroll
        for (int nt2 = 0; nt2 < 2; nt2++)
            LDSM4(bh2[nt2], sKH + bOff + (uint32_t)nt2*16*144 + cb);
        #pragma unroll
        for (int mt = 0; mt < 2; mt++)
            #pragma unroll
            for (int nt = 0; nt < 4; nt++)
                MMAF16(acc[mt][nt], ah[mt], bh2[nt>>1][nt&1], bh2[nt>>1][2+(nt&1)]);
    }

    const float scale = 0.35355339059327373f;  // 1/sqrt(8) batch-size quirk
    float* out = g_Sc + (size_t)h * S_ * S_;
    #pragma unroll
    for (int mt = 0; mt < 2; mt++) {
        #pragma unroll
        for (int half = 0; half < 2; half++) {
            const int q = qt*64 + wm*32 + mt*16 + (lane >> 2) + half*8;
            #pragma unroll
            for (int nt = 0; nt < 4; nt++) {
                const int k0 = kt*64 + wn*32 + nt*8 + (lane & 3)*2;
                float v0 = acc[mt][nt][half*2]     * scale;
                float v1 = acc[mt][nt][half*2 + 1] * scale;
                if (k0     > q || v0 == 0.0f) v0 = -1e9f;
                if (k0 + 1 > q || v1 == 0.0f) v1 = -1e9f;
                *(float2*)(out + (size_t)q * S_ + k0) = make_float2(v0, v1);
            }
        }
    }
}

// ---------------- softmax over heads -> fp16 attn (hi only), per-batch -----
__global__ void softmax_h_kernel(int b)
{
    const int k = blockIdx.x * 256 + threadIdx.x;
    const int q = blockIdx.y;
    const int kmax = ((q >> 6) + 1) << 6;
    if (k >= kmax) return;

    const size_t so = (size_t)q * S_ + k;
    const size_t hs = (size_t)S_ * S_;
    float s[H_];
    float m = -3.4e38f;
    #pragma unroll
    for (int h = 0; h < H_; h++) { s[h] = g_Sc[so + h * hs]; m = fmaxf(m, s[h]); }
    float Z = 0.f;
    #pragma unroll
    for (int h = 0; h < H_; h++) { s[h] = __expf(s[h] - m); Z += s[h]; }
    const float inv = 1.0f / Z;
    const size_t ab = (size_t)b * H_ * S_ * S_ + so;
    #pragma unroll
    for (int h = 0; h < H_; h++)
        g_Ah[ab + h * hs] = __float2half_rn(s[h] * inv);
}

// ---------------- V tile sums (from transposed fp16 V) + prefix scan -------
__global__ void tilesum_kernel()
{
    const int blk = blockIdx.x;
    const int e = threadIdx.x;
    const int tt = blk & (NT_ - 1);
    const int bh = blk / NT_;
    const __half2* Vb = (const __half2*)(g_Vth + (((size_t)bh * 64 + e) << 10) + tt*64);
    float sum = 0.f;
    #pragma unroll
    for (int k = 0; k < 32; k++) {
        const __half2 v = Vb[k];
        sum += __half2float(v.x) + __half2float(v.y);
    }
    g_TS[((size_t)bh * NT_ + tt) * E_ + e] = sum;
}

__global__ void scan_kernel()
{
    const int id = blockIdx.x * 256 + threadIdx.x;
    const int e = id & 63, bh = id >> 6;
    float* P = g_P + (size_t)bh * (NT_ + 1) * E_;
    float p = 0.f;
    P[e] = 0.f;
    #pragma unroll
    for (int tt = 0; tt < NT_; tt++) {
        p += g_TS[((size_t)bh * NT_ + tt) * E_ + e];
        P[(tt + 1) * E_ + e] = p;
    }
}

// ---------------- attn @ V via mma + masked suffix (single launch) ---------
__global__ __launch_bounds__(128) void attnv_mma_kernel()
{
    const int qt = blockIdx.x, bh = blockIdx.y;
    const int b = bh >> 4, h = bh & 15;

    __shared__ __align__(16) char sm[2 * 64 * 144];
    const uint32_t sAH = smem_u32(sm);
    const uint32_t sVH = sAH + 9216;

    const int tid = threadIdx.x;
    const int lane = tid & 31, wid = tid >> 5;
    const int wm = wid >> 1, wn = wid & 1;

    float acc[2][4][4];
    #pragma unroll
    for (int a = 0; a < 2; a++)
        #pragma unroll
        for (int b2 = 0; b2 < 4; b2++)
            #pragma unroll
            for (int c = 0; c < 4; c++) acc[a][b2][c] = 0.f;

    const uint32_t aOff = (uint32_t)(wm*32 + (lane & 15)) * 144 + ((lane >> 4) << 4);
    const uint32_t bOff = (uint32_t)(wn*32 + ((lane >> 3) & 1)*8 + (lane & 7)) * 144 + ((lane >> 4) << 4);

    const __half* gAH0 = g_Ah + ((size_t)bh * 1024 + qt*64) * 1024;
    const __half* gVH0 = g_Vth + (size_t)bh * 64 * 1024;

    for (int kt = 0; kt <= qt; kt++) {
        __syncthreads();
        #pragma unroll
        for (int i = tid; i < 512; i += 128) {
            const int r = i >> 3, c = i & 7;
            const size_t go = (size_t)r * 1024 + kt*64 + c * 8;
            const uint32_t so = r * 144 + c * 16;
            *(uint4*)(sm + so)        = *(const uint4*)(gAH0 + go);
            *(uint4*)(sm + 9216 + so) = *(const uint4*)(gVH0 + go);
        }
        __syncthreads();

        #pragma unroll
        for (int ks = 0; ks < 4; ks++) {
            const uint32_t cb = ks * 32;
            uint32_t ah[2][4], vh[2][4];
            #pragma unroll
            for (int mt = 0; mt < 2; mt++)
                LDSM4(ah[mt], sAH + aOff + (uint32_t)mt*16*144 + cb);
            #pragma unroll
            for (int nt2 = 0; nt2 < 2; nt2++)
                LDSM4(vh[nt2], sVH + bOff + (uint32_t)nt2*16*144 + cb);
            #pragma unroll
            for (int mt = 0; mt < 2; mt++)
                #pragma unroll
                for (int nt = 0; nt < 4; nt++)
                    MMAF16(acc[mt][nt], ah[mt], vh[nt>>1][nt&1], vh[nt>>1][2+(nt&1)]);
        }
    }

    const float* P = g_P + (size_t)bh * (NT_ + 1) * E_;
    #pragma unroll
    for (int nt = 0; nt < 4; nt++) {
        const int e0 = wn*32 + nt*8 + (lane & 3)*2;
        const float s0 = (P[NT_*E_ + e0]     - P[(qt+1)*E_ + e0])     * 0.0625f;
        const float s1 = (P[NT_*E_ + e0 + 1] - P[(qt+1)*E_ + e0 + 1]) * 0.0625f;
        #pragma unroll
        for (int mt = 0; mt < 2; mt++) {
            #pragma unroll
            for (int half = 0; half < 2; half++) {
                const int q = wm*32 + mt*16 + (lane >> 2) + half*8;
                __half* base = g_AOh + ((size_t)(b*1024 + qt*64 + q)) * D_ + h*64 + e0;
                *(__half2*)(base) = __half2(
                    __float2half_rn(acc[mt][nt][half*2]     + s0),
                    __float2half_rn(acc[mt][nt][half*2 + 1] + s1));
            }
        }
    }
}

// ---------------- launch ---------------------------------------------------
extern "C" void kernel_launch(void* const* d_in, const int* in_sizes, int n_in,
                              void* d_out, int out_size)
{
    const float* X1 = (const float*)d_in[0];
    const float* X2 = (const float*)d_in[1];
    const float* Wq = (const float*)d_in[2];
    const float* bq = (const float*)d_in[3];
    const float* Wk = (const float*)d_in[4];
    const float* bk = (const float*)d_in[5];
    const float* Wv = (const float*)d_in[6];
    const float* bv = (const float*)d_in[7];
    const float* Wo = (const float*)d_in[8];
    const float* bo = (const float*)d_in[9];
    float* out = (float*)d_out;

    void *pX1h, *pX2h, *pAOh, *pWqkv, *pWo;
    void *pQh, *pKh, *pVth;
    cudaGetSymbolAddress(&pX1h, g_X1h); cudaGetSymbolAddress(&pX2h, g_X2h);
    cudaGetSymbolAddress(&pAOh, g_AOh);
    cudaGetSymbolAddress(&pWqkv, g_Wqkv); cudaGetSymbolAddress(&pWo, g_Wo);
    cudaGetSymbolAddress(&pQh, g_Qh); cudaGetSymbolAddress(&pKh, g_Kh);
    cudaGetSymbolAddress(&pVth, g_Vth);

    const uint32_t SMEM_G = 61440;
    cudaFuncSetAttribute(gemm_mma_kernel,
                         cudaFuncAttributeMaxDynamicSharedMemorySize, SMEM_G);

    const int n4x = BS_ * D_ / 4;
    cvt_h_kernel<<<n4x / 256, 256>>>(X1, (__half*)pX1h, n4x);
    cvt_h_kernel<<<n4x / 256, 256>>>(X2, (__half*)pX2h, n4x);

    const dim3 gT(32, 32), bT(32, 8);
    pack_w_kernel<<<gT, bT>>>(Wq, (__half*)pWqkv);
    pack_w_kernel<<<gT, bT>>>(Wk, (__half*)pWqkv + (size_t)1024*1024);
    pack_w_kernel<<<gT, bT>>>(Wv, (__half*)pWqkv + (size_t)2*1024*1024);
    pack_w_kernel<<<gT, bT>>>(Wo, (__half*)pWo);

    // single fused Q+K+V projection launch (1536 CTAs)
    gemm_mma_kernel<<<dim3(24, 64), 256, SMEM_G>>>(
        (__half*)pX1h, (__half*)pX2h, (__half*)pWqkv,
        bq, bk, bv, nullptr,
        (__half*)pQh, (__half*)pKh, (__half*)pVth, 5);

    tilesum_kernel<<<B_ * H_ * NT_, 64>>>();
    scan_kernel<<<(B_ * H_ * E_) / 256, 256>>>();

    // per-batch scores -> softmax on L2-resident scratch
    for (int b = 0; b < B_; b++) {
        scores_mma_kernel<<<dim3(NT_, NT_, H_), 128>>>(b);
        softmax_h_kernel<<<dim3(S_ / 256, S_, 1), 256>>>(b);
    }

    // attn @ V: single full-parallelism launch
    attnv_mma_kernel<<<dim3(NT_, B_ * H_), 128>>>();

    // output projection: plain K=1024
    gemm_mma_kernel<<<dim3(8, 64), 256, SMEM_G>>>(
        (__half*)pAOh, nullptr, (__half*)pWo,
        bo, nullptr, nullptr, out,
        nullptr, nullptr, nullptr, 0);
}